// round 2
// baseline (speedup 1.0000x reference)
#include <cuda_runtime.h>
#include <math.h>

#define Bb 4
#define Nn 2047
#define N1 2048
#define Ii 256
#define Oo 128
#define Hh 4
#define SLOPEF 0.2f

// ---------------- scratch (device globals; no allocation allowed) ----------------
__device__ float g_hp[Bb * N1 * Oo];            // 4 MB   concat(self_linear(x), prior)
__device__ float g_hph[Bb * Hh * N1 * Oo];      // 16 MB  per-head projection
__device__ float g_ssrc[Bb * Hh * N1];
__device__ float g_sdst[Bb * Hh * N1];
__device__ float g_Ej[Bb * Hh * N1];            // exp(s_dst) (0 if masked col)
__device__ float g_Fj[Bb * Hh * N1];            // exp(0.2*s_dst) (0 if masked col)
__device__ float g_meanhp[Bb * Hh * Oo];        // mean over nodes of hph (masked-row output)
__device__ float g_outH[Bb * Hh * N1 * Oo];     // 16 MB  per-head attention output
__device__ int g_mask_is_int;                   // 1 if x_mask stored as int32, 0 if 1-byte

// ---------------- mask dtype detection ----------------
__global__ void kinit_maskflag() { g_mask_is_int = 1; }

__global__ void kdetect_mask(const unsigned* __restrict__ m) {
    // reads first 2048 words = 8192 bytes (safe for both layouts).
    // int32 bool data: every word is 0 or 1. byte bool data: words are packed
    // 0x00/0x01 bytes; any value > 1 proves byte layout.
    int idx = blockIdx.x * 256 + threadIdx.x;   // grid 8 -> 2048
    if (m[idx] > 1u) g_mask_is_int = 0;
}

__device__ __forceinline__ bool mask_at(const void* m, int idx) {
    if (g_mask_is_int) return ((const int*)m)[idx] != 0;
    return ((const unsigned char*)m)[idx] != 0;
}

// ---------------- K1: hp[b,n,o] = sum_i x[b,n,i]*W[o,i]; row N1-1 = prior ----------------
__global__ __launch_bounds__(256) void k1_selflinear(const float* __restrict__ x,
                                                     const float* __restrict__ prior,
                                                     const float* __restrict__ Wlin) {
    __shared__ float xs[32][33];
    __shared__ float ws[128][33];
    const int b = blockIdx.y;
    const int nb = blockIdx.x * 32;
    const int t = threadIdx.x;
    const int tr = t >> 5;   // 0..7 -> rows 4*tr+a
    const int tc = t & 31;   // cols tc + 32*c

    float acc[4][4];
#pragma unroll
    for (int a = 0; a < 4; ++a)
#pragma unroll
        for (int c = 0; c < 4; ++c) acc[a][c] = 0.f;

    for (int kb = 0; kb < Ii; kb += 32) {
        __syncthreads();
#pragma unroll
        for (int it = 0; it < 4; ++it) {
            int idx = t + 256 * it;
            int r = idx >> 5, k = idx & 31;
            int gn = nb + r;
            xs[r][k] = (gn < Nn) ? x[(b * Nn + gn) * Ii + kb + k] : 0.f;
        }
#pragma unroll
        for (int it = 0; it < 16; ++it) {
            int idx = t + 256 * it;
            int p = idx >> 5, k = idx & 31;
            ws[p][k] = Wlin[p * Ii + kb + k];
        }
        __syncthreads();
#pragma unroll
        for (int k = 0; k < 32; ++k) {
            float xv[4], wv[4];
#pragma unroll
            for (int a = 0; a < 4; ++a) xv[a] = xs[4 * tr + a][k];
#pragma unroll
            for (int c = 0; c < 4; ++c) wv[c] = ws[tc + 32 * c][k];
#pragma unroll
            for (int a = 0; a < 4; ++a)
#pragma unroll
                for (int c = 0; c < 4; ++c) acc[a][c] = fmaf(xv[a], wv[c], acc[a][c]);
        }
    }
#pragma unroll
    for (int a = 0; a < 4; ++a) {
        int gn = nb + 4 * tr + a;
#pragma unroll
        for (int c = 0; c < 4; ++c) {
            int col = tc + 32 * c;
            g_hp[(b * N1 + gn) * Oo + col] = (gn == Nn) ? prior[b * Oo + col] : acc[a][c];
        }
    }
}

// ---------------- K2: hph[b,h,n,p] = sum_o hp[b,n,o]*w_head[h,o,p] ----------------
__global__ __launch_bounds__(256) void k2_headproj(const float* __restrict__ whead) {
    __shared__ float as_[32][33];
    __shared__ float ws[32][128];
    const int nb = blockIdx.x * 32;
    const int h = blockIdx.y;
    const int b = blockIdx.z;
    const int t = threadIdx.x;
    const int tr = t >> 5;
    const int tc = t & 31;

    float acc[4][4];
#pragma unroll
    for (int a = 0; a < 4; ++a)
#pragma unroll
        for (int c = 0; c < 4; ++c) acc[a][c] = 0.f;

    for (int kb = 0; kb < Oo; kb += 32) {
        __syncthreads();
#pragma unroll
        for (int it = 0; it < 4; ++it) {
            int idx = t + 256 * it;
            int r = idx >> 5, k = idx & 31;
            as_[r][k] = g_hp[(b * N1 + nb + r) * Oo + kb + k];
        }
#pragma unroll
        for (int it = 0; it < 16; ++it) {
            int idx = t + 256 * it;
            int o = idx >> 7, p = idx & 127;
            ws[o][p] = whead[(h * Oo + kb + o) * Oo + p];
        }
        __syncthreads();
#pragma unroll
        for (int k = 0; k < 32; ++k) {
            float xv[4], wv[4];
#pragma unroll
            for (int a = 0; a < 4; ++a) xv[a] = as_[4 * tr + a][k];
#pragma unroll
            for (int c = 0; c < 4; ++c) wv[c] = ws[k][tc + 32 * c];
#pragma unroll
            for (int a = 0; a < 4; ++a)
#pragma unroll
                for (int c = 0; c < 4; ++c) acc[a][c] = fmaf(xv[a], wv[c], acc[a][c]);
        }
    }
    const int bh = b * Hh + h;
#pragma unroll
    for (int a = 0; a < 4; ++a) {
        int gn = nb + 4 * tr + a;
#pragma unroll
        for (int c = 0; c < 4; ++c)
            g_hph[(bh * N1 + gn) * Oo + tc + 32 * c] = acc[a][c];
    }
}

// ---------------- K3: s_src/s_dst via tanh-dot; Ej/Fj factors ----------------
__global__ __launch_bounds__(128) void k3_scores(const float* __restrict__ asrc,
                                                 const float* __restrict__ adst,
                                                 const void* __restrict__ xmask) {
    const int n = blockIdx.x;
    const int h = blockIdx.y;
    const int b = blockIdx.z;
    const int t = threadIdx.x;
    const int bh = b * Hh + h;

    float v = g_hph[(bh * N1 + n) * Oo + t];
    float tv = tanhf(v);
    float ps = tv * asrc[h * Oo + t];
    float pd = tv * adst[h * Oo + t];
#pragma unroll
    for (int off = 16; off; off >>= 1) {
        ps += __shfl_xor_sync(0xffffffffu, ps, off);
        pd += __shfl_xor_sync(0xffffffffu, pd, off);
    }
    __shared__ float shs[4], shd[4];
    if ((t & 31) == 0) { shs[t >> 5] = ps; shd[t >> 5] = pd; }
    __syncthreads();
    if (t == 0) {
        float ss = shs[0] + shs[1] + shs[2] + shs[3];
        float sd = shd[0] + shd[1] + shd[2] + shd[3];
        int idx = bh * N1 + n;
        g_ssrc[idx] = ss;
        g_sdst[idx] = sd;
        bool mj = mask_at(xmask, b * N1 + n);
        g_Ej[idx] = mj ? 0.f : expf(sd);
        g_Fj[idx] = mj ? 0.f : expf(SLOPEF * sd);
    }
}

// ---------------- K3b: meanhp[b,h,p] over all N1 nodes ----------------
__global__ __launch_bounds__(128) void k3b_meanhp() {
    const int h = blockIdx.x;
    const int b = blockIdx.y;
    const int t = threadIdx.x;
    const int bh = b * Hh + h;
    const float* p = g_hph + (size_t)bh * N1 * Oo + t;
    float s0 = 0.f, s1 = 0.f, s2 = 0.f, s3 = 0.f;
    for (int n = 0; n < N1; n += 4) {
        s0 += p[(n + 0) * Oo];
        s1 += p[(n + 1) * Oo];
        s2 += p[(n + 2) * Oo];
        s3 += p[(n + 3) * Oo];
    }
    g_meanhp[bh * Oo + t] = (s0 + s1 + s2 + s3) * (1.f / (float)N1);
}

// ---------------- K4: flash-style attention + weighted sum (f32x2 FMA) ----------------
__global__ __launch_bounds__(256) void k4_attn(const void* __restrict__ xmask) {
    __shared__ float hps[32][128];   // hph j-tile
    __shared__ float ps[32][33];     // p j-tile [jl][row], padded
    __shared__ float sis[32], Eis[32], Fis[32], ls[32];
    __shared__ unsigned char runi[32];
    __shared__ float red8[8];

    const int ib = blockIdx.x;
    const int h = blockIdx.y;
    const int b = blockIdx.z;
    const int t = threadIdx.x;
    const int bh = b * Hh + h;

    const float* sdst = g_sdst + bh * N1;
    const float* Ejp = g_Ej + bh * N1;
    const float* Fjp = g_Fj + bh * N1;
    const float* hph = g_hph + (size_t)bh * N1 * Oo;

    // ---- Mdst = max over unmasked j of s_dst ----
    float mx = -INFINITY;
    for (int j = t; j < N1; j += 256) {
        float sv = sdst[j];
        if (!mask_at(xmask, b * N1 + j)) mx = fmaxf(mx, sv);
    }
#pragma unroll
    for (int off = 16; off; off >>= 1) mx = fmaxf(mx, __shfl_xor_sync(0xffffffffu, mx, off));
    if ((t & 31) == 0) red8[t >> 5] = mx;
    __syncthreads();
    if (t == 0) {
        float m = red8[0];
#pragma unroll
        for (int i = 1; i < 8; ++i) m = fmaxf(m, red8[i]);
        red8[0] = m;
    }
    __syncthreads();
    const float Mdst = red8[0];

    // ---- row constants ----
    if (t < 32) {
        int gn = ib * 32 + t;
        float si = g_ssrc[bh * N1 + gn];
        bool mrow = mask_at(xmask, b * N1 + gn);
        bool nou = (Mdst == -INFINITY);
        float xm = si + Mdst;
        float m = (xm >= 0.f) ? xm : SLOPEF * xm;   // = max_j lrelu(si+sj) (lrelu monotone)
        sis[t] = si;
        Eis[t] = expf(si - m);
        Fis[t] = expf(SLOPEF * si - m);
        runi[t] = (mrow || nou) ? 1 : 0;
    }
    __syncthreads();

    // GEMM mapping: rows {tr, tr+16}, col pairs {2tc+32c}
    const int tr = t >> 4;   // 0..15
    const int tc = t & 15;   // 0..15
    // p-gen mapping: column jl, rows rw+8a
    const int jl = t & 31;
    const int rw = t >> 5;

    unsigned long long acc[2][4];
#pragma unroll
    for (int ar = 0; ar < 2; ++ar)
#pragma unroll
        for (int c = 0; c < 4; ++c) acc[ar][c] = 0ull;
    float lpart[4] = {0.f, 0.f, 0.f, 0.f};

    for (int jb = 0; jb < N1; jb += 32) {
        __syncthreads();
        // stage hph tile (coalesced float4)
        {
            const float4* src = (const float4*)(hph + (size_t)jb * Oo);
            float4* dst = (float4*)&hps[0][0];
#pragma unroll
            for (int it = 0; it < 4; ++it) dst[t + 256 * it] = src[t + 256 * it];
        }
        // p tile + l partials
        {
            int j = jb + jl;
            float sd = sdst[j];
            float E = Ejp[j];
            float F = Fjp[j];
#pragma unroll
            for (int a = 0; a < 4; ++a) {
                int r = rw + 8 * a;
                float xv = sis[r] + sd;
                float p = (xv >= 0.f) ? Eis[r] * E : Fis[r] * F;
                ps[jl][r] = p;
                lpart[a] += p;
            }
        }
        __syncthreads();
        // micro-GEMM: acc[row][col] += p[row][k] * hph[k][col], f32x2 packed
#pragma unroll
        for (int k = 0; k < 32; ++k) {
            float p0 = ps[k][tr];
            float p1 = ps[k][tr + 16];
            unsigned long long pp0, pp1;
            asm("mov.b64 %0, {%1, %1};" : "=l"(pp0) : "f"(p0));
            asm("mov.b64 %0, {%1, %1};" : "=l"(pp1) : "f"(p1));
#pragma unroll
            for (int c = 0; c < 4; ++c) {
                unsigned long long hv = *(const unsigned long long*)&hps[k][2 * tc + 32 * c];
                asm("fma.rn.f32x2 %0, %1, %2, %3;" : "=l"(acc[0][c]) : "l"(pp0), "l"(hv), "l"(acc[0][c]));
                asm("fma.rn.f32x2 %0, %1, %2, %3;" : "=l"(acc[1][c]) : "l"(pp1), "l"(hv), "l"(acc[1][c]));
            }
        }
    }

    // ---- reduce l over the 32 j-lanes of each warp (warp rw owns rows rw+8a) ----
#pragma unroll
    for (int a = 0; a < 4; ++a) {
        float v = lpart[a];
#pragma unroll
        for (int off = 16; off; off >>= 1) v += __shfl_xor_sync(0xffffffffu, v, off);
        if (jl == 0) ls[rw + 8 * a] = v;
    }
    __syncthreads();

    // ---- finalize: normalize, masked rows -> meanhp ----
    const float* mh = g_meanhp + bh * Oo;
    float* outp = g_outH + ((size_t)bh * N1 + ib * 32) * Oo;
#pragma unroll
    for (int ar = 0; ar < 2; ++ar) {
        int r = tr + 16 * ar;
        float inv = 1.f / ls[r];
        bool uni = runi[r] != 0;
#pragma unroll
        for (int c = 0; c < 4; ++c) {
            float lo, hi;
            asm("mov.b64 {%0, %1}, %2;" : "=f"(lo), "=f"(hi) : "l"(acc[ar][c]));
            int col = 2 * tc + 32 * c;
            outp[r * Oo + col] = uni ? mh[col] : lo * inv;
            outp[r * Oo + col + 1] = uni ? mh[col + 1] : hi * inv;
        }
    }
}

// ---------------- K5: mean over heads + bias ----------------
__global__ __launch_bounds__(256) void k5_mean(const float* __restrict__ bias,
                                               float* __restrict__ out) {
    int idx = blockIdx.x * 256 + threadIdx.x;  // over Bb*N1*Oo
    int col = idx & 127;
    int bn = idx >> 7;
    int b = bn >> 11;
    int n = bn & 2047;
    float s = 0.f;
#pragma unroll
    for (int h = 0; h < Hh; ++h)
        s += g_outH[(((size_t)(b * Hh + h)) * N1 + n) * Oo + col];
    out[idx] = 0.25f * s + bias[col];
}

// ---------------- launch ----------------
extern "C" void kernel_launch(void* const* d_in, const int* in_sizes, int n_in,
                              void* d_out, int out_size) {
    const float* x = (const float*)d_in[0];
    const float* prior = (const float*)d_in[1];
    const void* xmask = d_in[2];
    const float* Wlin = (const float*)d_in[3];
    const float* whead = (const float*)d_in[4];
    const float* asrc = (const float*)d_in[5];
    const float* adst = (const float*)d_in[6];
    const float* bias = (const float*)d_in[7];
    float* out = (float*)d_out;

    kinit_maskflag<<<1, 1>>>();
    kdetect_mask<<<8, 256>>>((const unsigned*)xmask);
    k1_selflinear<<<dim3(64, Bb), 256>>>(x, prior, Wlin);
    k2_headproj<<<dim3(64, Hh, Bb), 256>>>(whead);
    k3_scores<<<dim3(N1, Hh, Bb), 128>>>(asrc, adst, xmask);
    k3b_meanhp<<<dim3(Hh, Bb), 128>>>();
    k4_attn<<<dim3(64, Hh, Bb), 256>>>(xmask);
    k5_mean<<<(Bb * N1 * Oo) / 256, 256>>>(bias, out);
}

// round 3
// speedup vs baseline: 1.0069x; 1.0069x over previous
#include <cuda_runtime.h>
#include <math.h>

#define Bb 4
#define Nn 2047
#define N1 2048
#define Ii 256
#define Oo 128
#define Hh 4
#define SLOPEF 0.2f

// ---------------- scratch (device globals; no allocation allowed) ----------------
__device__ float g_hp[Bb * N1 * Oo];            // 4 MB   concat(self_linear(x), prior)
__device__ float g_hph[Bb * Hh * N1 * Oo];      // 16 MB  per-head projection
__device__ float g_ssrc[Bb * Hh * N1];
__device__ float g_sdst[Bb * Hh * N1];
__device__ float g_Ej[Bb * Hh * N1];            // exp(s_dst) (0 if masked col)
__device__ float g_Fj[Bb * Hh * N1];            // exp(0.2*s_dst) (0 if masked col)
__device__ float g_Ei[Bb * Hh * N1];            // row factor exp(si - m) (0 if uniform row)
__device__ float g_Fi[Bb * Hh * N1];            // row factor exp(0.2 si - m)
__device__ unsigned char g_runi[Bb * Hh * N1];  // row-uniform flag
__device__ float g_mhp0[Bb * Oo];               // mean over n of hp
__device__ float g_meanhp[Bb * Hh * Oo];        // mean over nodes of hph (masked-row output)
__device__ int g_mask_is_int;                   // 1 if x_mask stored as int32, 0 if 1-byte

// ---------------- mask dtype detection ----------------
__global__ void kinit_maskflag() { g_mask_is_int = 1; }

__global__ void kdetect_mask(const unsigned* __restrict__ m) {
    // int32 bool data: every word is 0/1. byte bool data: packed bytes give words > 1.
    int idx = blockIdx.x * 256 + threadIdx.x;   // grid 8 -> 2048 words = 8192 bytes
    if (m[idx] > 1u) g_mask_is_int = 0;
}

__device__ __forceinline__ bool mask_at(const void* m, int idx) {
    if (g_mask_is_int) return ((const int*)m)[idx] != 0;
    return ((const unsigned char*)m)[idx] != 0;
}

// fast accurate tanh: (e^2x - 1) / (e^2x + 1), clamped (rel err ~1e-6)
__device__ __forceinline__ float fast_tanh(float x) {
    float cx = fminf(fmaxf(x, -15.f), 15.f);
    float e = __expf(2.f * cx);
    return __fdividef(e - 1.f, e + 1.f);
}

// ---------------- K1: hp[b,n,o] = sum_i x[b,n,i]*W[o,i]; row N1-1 = prior ----------------
__global__ __launch_bounds__(256) void k1_selflinear(const float* __restrict__ x,
                                                     const float* __restrict__ prior,
                                                     const float* __restrict__ Wlin) {
    __shared__ float xs[32][33];
    __shared__ float ws[128][33];
    const int b = blockIdx.y;
    const int nb = blockIdx.x * 32;
    const int t = threadIdx.x;
    const int tr = t >> 5;
    const int tc = t & 31;

    float acc[4][4];
#pragma unroll
    for (int a = 0; a < 4; ++a)
#pragma unroll
        for (int c = 0; c < 4; ++c) acc[a][c] = 0.f;

    for (int kb = 0; kb < Ii; kb += 32) {
        __syncthreads();
#pragma unroll
        for (int it = 0; it < 4; ++it) {
            int idx = t + 256 * it;
            int r = idx >> 5, k = idx & 31;
            int gn = nb + r;
            xs[r][k] = (gn < Nn) ? x[(b * Nn + gn) * Ii + kb + k] : 0.f;
        }
#pragma unroll
        for (int it = 0; it < 16; ++it) {
            int idx = t + 256 * it;
            int p = idx >> 5, k = idx & 31;
            ws[p][k] = Wlin[p * Ii + kb + k];
        }
        __syncthreads();
#pragma unroll
        for (int k = 0; k < 32; ++k) {
            float xv[4], wv[4];
#pragma unroll
            for (int a = 0; a < 4; ++a) xv[a] = xs[4 * tr + a][k];
#pragma unroll
            for (int c = 0; c < 4; ++c) wv[c] = ws[tc + 32 * c][k];
#pragma unroll
            for (int a = 0; a < 4; ++a)
#pragma unroll
                for (int c = 0; c < 4; ++c) acc[a][c] = fmaf(xv[a], wv[c], acc[a][c]);
        }
    }
#pragma unroll
    for (int a = 0; a < 4; ++a) {
        int gn = nb + 4 * tr + a;
#pragma unroll
        for (int c = 0; c < 4; ++c) {
            int col = tc + 32 * c;
            g_hp[(b * N1 + gn) * Oo + col] = (gn == Nn) ? prior[b * Oo + col] : acc[a][c];
        }
    }
}

// ---------------- K2: hph + fused tanh-dot scores + Ej/Fj ----------------
__global__ __launch_bounds__(256) void k2_headproj(const float* __restrict__ whead,
                                                   const float* __restrict__ asrc,
                                                   const float* __restrict__ adst,
                                                   const void* __restrict__ xmask) {
    __shared__ float as_[32][33];
    __shared__ float ws[32][128];
    const int nb = blockIdx.x * 32;
    const int h = blockIdx.y;
    const int b = blockIdx.z;
    const int t = threadIdx.x;
    const int tr = t >> 5;   // warp id -> rows 4*tr+a
    const int tc = t & 31;   // lane -> cols tc + 32*c

    float acc[4][4];
#pragma unroll
    for (int a = 0; a < 4; ++a)
#pragma unroll
        for (int c = 0; c < 4; ++c) acc[a][c] = 0.f;

    for (int kb = 0; kb < Oo; kb += 32) {
        __syncthreads();
#pragma unroll
        for (int it = 0; it < 4; ++it) {
            int idx = t + 256 * it;
            int r = idx >> 5, k = idx & 31;
            as_[r][k] = g_hp[(b * N1 + nb + r) * Oo + kb + k];
        }
#pragma unroll
        for (int it = 0; it < 16; ++it) {
            int idx = t + 256 * it;
            int o = idx >> 7, p = idx & 127;
            ws[o][p] = whead[(h * Oo + kb + o) * Oo + p];
        }
        __syncthreads();
#pragma unroll
        for (int k = 0; k < 32; ++k) {
            float xv[4], wv[4];
#pragma unroll
            for (int a = 0; a < 4; ++a) xv[a] = as_[4 * tr + a][k];
#pragma unroll
            for (int c = 0; c < 4; ++c) wv[c] = ws[k][tc + 32 * c];
#pragma unroll
            for (int a = 0; a < 4; ++a)
#pragma unroll
                for (int c = 0; c < 4; ++c) acc[a][c] = fmaf(xv[a], wv[c], acc[a][c]);
        }
    }
    const int bh = b * Hh + h;
    // store hph + fused scores epilogue
#pragma unroll
    for (int a = 0; a < 4; ++a) {
        int gn = nb + 4 * tr + a;
        float ps = 0.f, pd = 0.f;
#pragma unroll
        for (int c = 0; c < 4; ++c) {
            int col = tc + 32 * c;
            float v = acc[a][c];
            g_hph[(bh * N1 + gn) * Oo + col] = v;
            float tv = fast_tanh(v);
            ps = fmaf(tv, asrc[h * Oo + col], ps);
            pd = fmaf(tv, adst[h * Oo + col], pd);
        }
#pragma unroll
        for (int off = 16; off; off >>= 1) {
            ps += __shfl_xor_sync(0xffffffffu, ps, off);
            pd += __shfl_xor_sync(0xffffffffu, pd, off);
        }
        if (tc == 0) {
            int idx = bh * N1 + gn;
            g_ssrc[idx] = ps;
            g_sdst[idx] = pd;
            bool mj = mask_at(xmask, b * N1 + gn);
            g_Ej[idx] = mj ? 0.f : expf(pd);
            g_Fj[idx] = mj ? 0.f : expf(SLOPEF * pd);
        }
    }
}

// ---------------- K2b: mhp0[b,o] = mean over n of hp ----------------
__global__ __launch_bounds__(1024) void k2b_meanhp0() {
    __shared__ float red[1024];
    const int b = blockIdx.x;
    const int t = threadIdx.x;
    const int col = t & 127;
    const int seg = t >> 7;   // 0..7
    const float* p = g_hp + ((size_t)b * N1 + seg * 256) * Oo + col;
    float s = 0.f;
#pragma unroll 4
    for (int i = 0; i < 256; ++i) s += p[i * Oo];
    red[t] = s;
    __syncthreads();
    if (t < 128) {
        float tot = 0.f;
#pragma unroll
        for (int sgi = 0; sgi < 8; ++sgi) tot += red[col + 128 * sgi];
        g_mhp0[b * Oo + col] = tot * (1.f / (float)N1);
    }
}

// ---------------- K2c: meanhp[b,h,p] = mhp0[b] @ w_head[h] ----------------
__global__ __launch_bounds__(128) void k2c_meanhp(const float* __restrict__ whead) {
    __shared__ float m0[Oo];
    const int h = blockIdx.x;
    const int b = blockIdx.y;
    const int t = threadIdx.x;
    m0[t] = g_mhp0[b * Oo + t];
    __syncthreads();
    float s = 0.f;
#pragma unroll 8
    for (int o = 0; o < Oo; ++o) s = fmaf(m0[o], whead[(h * Oo + o) * Oo + t], s);
    g_meanhp[(b * Hh + h) * Oo + t] = s;
}

// ---------------- K3m: per-(b,h) Mdst + row factors Ei/Fi/runi ----------------
__global__ __launch_bounds__(256) void k3m_rowfac() {
    __shared__ float red8[8];
    const int h = blockIdx.x;
    const int b = blockIdx.y;
    const int t = threadIdx.x;
    const int bh = b * Hh + h;
    const float* sdst = g_sdst + bh * N1;
    const float* Ej = g_Ej + bh * N1;

    float mx = -INFINITY;
    for (int n = t; n < N1; n += 256)
        if (Ej[n] > 0.f) mx = fmaxf(mx, sdst[n]);
#pragma unroll
    for (int off = 16; off; off >>= 1) mx = fmaxf(mx, __shfl_xor_sync(0xffffffffu, mx, off));
    if ((t & 31) == 0) red8[t >> 5] = mx;
    __syncthreads();
    if (t == 0) {
        float m = red8[0];
#pragma unroll
        for (int i = 1; i < 8; ++i) m = fmaxf(m, red8[i]);
        red8[0] = m;
    }
    __syncthreads();
    const float Mdst = red8[0];
    const bool nou = (Mdst == -INFINITY);

    for (int n = t; n < N1; n += 256) {
        int idx = bh * N1 + n;
        float si = g_ssrc[idx];
        bool uni = nou || (Ej[n] == 0.f);
        float xm = si + Mdst;
        float m = (xm >= 0.f) ? xm : SLOPEF * xm;   // max_j lrelu(si+sj) (lrelu monotone)
        g_Ei[idx] = uni ? 0.f : expf(si - m);
        g_Fi[idx] = uni ? 0.f : expf(SLOPEF * si - m);
        g_runi[idx] = uni ? 1 : 0;
    }
}

// ---------------- K4: flash-style attention, all heads, fused mean+bias ----------------
__global__ __launch_bounds__(256) void k4_attn(const float* __restrict__ bias,
                                               float* __restrict__ out) {
    __shared__ float hps[32][128];   // hph j-tile
    __shared__ float ps[32][33];     // p tile [jl][row]
    __shared__ float sis[32], Eis[32], Fis[32], ls[32];
    __shared__ unsigned char runi[32];
    __shared__ float mhs[Oo];

    const int ib = blockIdx.x;
    const int b = blockIdx.y;
    const int t = threadIdx.x;

    // GEMM mapping: rows {tr, tr+16}, col pairs {2tc+32c}
    const int tr = t >> 4;
    const int tc = t & 15;
    // p-gen mapping: column jl, rows rw+8a
    const int jl = t & 31;
    const int rw = t >> 5;

    float sum[2][4][2];
#pragma unroll
    for (int ar = 0; ar < 2; ++ar)
#pragma unroll
        for (int c = 0; c < 4; ++c) { sum[ar][c][0] = 0.f; sum[ar][c][1] = 0.f; }

    for (int h = 0; h < Hh; ++h) {
        const int bh = b * Hh + h;
        const float* sdst = g_sdst + bh * N1;
        const float* Ejp = g_Ej + bh * N1;
        const float* Fjp = g_Fj + bh * N1;
        const float* hph = g_hph + (size_t)bh * N1 * Oo;

        __syncthreads();   // protect smem row constants from previous epilogue reads
        if (t < 32) {
            int idx = bh * N1 + ib * 32 + t;
            sis[t] = g_ssrc[idx];
            Eis[t] = g_Ei[idx];
            Fis[t] = g_Fi[idx];
            runi[t] = g_runi[idx];
        }
        if (t < Oo) mhs[t] = g_meanhp[bh * Oo + t];

        unsigned long long acc[2][4];
#pragma unroll
        for (int ar = 0; ar < 2; ++ar)
#pragma unroll
            for (int c = 0; c < 4; ++c) acc[ar][c] = 0ull;
        float lpart[4] = {0.f, 0.f, 0.f, 0.f};

        for (int jb = 0; jb < N1; jb += 32) {
            __syncthreads();
            {
                const float4* src = (const float4*)(hph + (size_t)jb * Oo);
                float4* dst = (float4*)&hps[0][0];
#pragma unroll
                for (int it = 0; it < 4; ++it) dst[t + 256 * it] = src[t + 256 * it];
            }
            {
                int j = jb + jl;
                float sd = sdst[j];
                float E = Ejp[j];
                float F = Fjp[j];
#pragma unroll
                for (int a = 0; a < 4; ++a) {
                    int r = rw + 8 * a;
                    float xv = sis[r] + sd;
                    float p = (xv >= 0.f) ? Eis[r] * E : Fis[r] * F;
                    ps[jl][r] = p;
                    lpart[a] += p;
                }
            }
            __syncthreads();
#pragma unroll
            for (int k = 0; k < 32; ++k) {
                float p0 = ps[k][tr];
                float p1 = ps[k][tr + 16];
                unsigned long long pp0, pp1;
                asm("mov.b64 %0, {%1, %1};" : "=l"(pp0) : "f"(p0));
                asm("mov.b64 %0, {%1, %1};" : "=l"(pp1) : "f"(p1));
#pragma unroll
                for (int c = 0; c < 4; ++c) {
                    unsigned long long hv = *(const unsigned long long*)&hps[k][2 * tc + 32 * c];
                    asm("fma.rn.f32x2 %0, %1, %2, %3;" : "=l"(acc[0][c]) : "l"(pp0), "l"(hv), "l"(acc[0][c]));
                    asm("fma.rn.f32x2 %0, %1, %2, %3;" : "=l"(acc[1][c]) : "l"(pp1), "l"(hv), "l"(acc[1][c]));
                }
            }
        }

        // reduce l over the 32 j-lanes of each warp (warp rw owns rows rw+8a)
#pragma unroll
        for (int a = 0; a < 4; ++a) {
            float v = lpart[a];
#pragma unroll
            for (int off = 16; off; off >>= 1) v += __shfl_xor_sync(0xffffffffu, v, off);
            if (jl == 0) ls[rw + 8 * a] = v;
        }
        __syncthreads();

        // accumulate this head's contribution
#pragma unroll
        for (int ar = 0; ar < 2; ++ar) {
            int r = tr + 16 * ar;
            float inv = 1.f / ls[r];
            bool uni = runi[r] != 0;
#pragma unroll
            for (int c = 0; c < 4; ++c) {
                float lo, hi;
                asm("mov.b64 {%0, %1}, %2;" : "=f"(lo), "=f"(hi) : "l"(acc[ar][c]));
                int col = 2 * tc + 32 * c;
                sum[ar][c][0] += uni ? mhs[col] : lo * inv;
                sum[ar][c][1] += uni ? mhs[col + 1] : hi * inv;
            }
        }
    }

    // final: mean over heads + bias
    float* outp = out + ((size_t)b * N1 + ib * 32) * Oo;
#pragma unroll
    for (int ar = 0; ar < 2; ++ar) {
        int r = tr + 16 * ar;
#pragma unroll
        for (int c = 0; c < 4; ++c) {
            int col = 2 * tc + 32 * c;
            outp[r * Oo + col] = 0.25f * sum[ar][c][0] + bias[col];
            outp[r * Oo + col + 1] = 0.25f * sum[ar][c][1] + bias[col + 1];
        }
    }
}

// ---------------- launch ----------------
extern "C" void kernel_launch(void* const* d_in, const int* in_sizes, int n_in,
                              void* d_out, int out_size) {
    const float* x = (const float*)d_in[0];
    const float* prior = (const float*)d_in[1];
    const void* xmask = d_in[2];
    const float* Wlin = (const float*)d_in[3];
    const float* whead = (const float*)d_in[4];
    const float* asrc = (const float*)d_in[5];
    const float* adst = (const float*)d_in[6];
    const float* bias = (const float*)d_in[7];
    float* out = (float*)d_out;

    kinit_maskflag<<<1, 1>>>();
    kdetect_mask<<<8, 256>>>((const unsigned*)xmask);
    k1_selflinear<<<dim3(64, Bb), 256>>>(x, prior, Wlin);
    k2_headproj<<<dim3(64, Hh, Bb), 256>>>(whead, asrc, adst, xmask);
    k2b_meanhp0<<<Bb, 1024>>>();
    k2c_meanhp<<<dim3(Hh, Bb), 128>>>(whead);
    k3m_rowfac<<<dim3(Hh, Bb), 256>>>();
    k4_attn<<<dim3(64, Bb), 256>>>(bias, out);
}

// round 4
// speedup vs baseline: 2.8386x; 2.8190x over previous
#include <cuda_runtime.h>
#include <math.h>

#define Bb 4
#define Nn 2047
#define N1 2048
#define Ii 256
#define Oo 128
#define Hh 4
#define SLOPEF 0.2f
#define NBH (Bb * Hh)
#define SEGS 8
#define SEGLEN 256
#define NP1 2049

// ---------------- scratch (device globals) ----------------
__device__ float g_hp[Bb * N1 * Oo];            // 4 MB
__device__ float g_hph[Bb * Hh * N1 * Oo];      // 16 MB
__device__ float g_ssrc[NBH * N1];
__device__ float g_sdst[NBH * N1];
__device__ float g_Ej[NBH * N1], g_Fj[NBH * N1];
__device__ float g_Ei[NBH * N1], g_Fi[NBH * N1];
__device__ unsigned char g_runi[NBH * N1];
__device__ float g_mhp0[Bb * Oo];
__device__ float g_meanhp[NBH * Oo];
__device__ float g_skey[NBH * N1];              // sorted s_dst
__device__ int   g_sidx[NBH * N1];
__device__ float g_wE[NBH * N1], g_wF[NBH * N1]; // Ej/Fj in sorted order
__device__ float g_SE[(size_t)NBH * NP1 * Oo];  // ~33.6 MB seg-local suffix scans of wE*hph
__device__ float g_PF[(size_t)NBH * NP1 * Oo];  // ~33.6 MB seg-local prefix scans of wF*hph
__device__ float g_sSE[NBH * NP1], g_sPF[NBH * NP1];
__device__ float g_offE[NBH * SEGS * Oo], g_offF[NBH * SEGS * Oo];
__device__ float g_soffE[NBH * SEGS], g_soffF[NBH * SEGS];
__device__ int g_mask_is_int;

// ---------------- mask dtype detection ----------------
__global__ void kinit_maskflag() { g_mask_is_int = 1; }
__global__ void kdetect_mask(const unsigned* __restrict__ m) {
    int idx = blockIdx.x * 256 + threadIdx.x;   // 2048 words = 8192 bytes, safe either way
    if (m[idx] > 1u) g_mask_is_int = 0;
}
__device__ __forceinline__ bool mask_at(const void* m, int idx) {
    if (g_mask_is_int) return ((const int*)m)[idx] != 0;
    return ((const unsigned char*)m)[idx] != 0;
}

__device__ __forceinline__ float fast_tanh(float x) {
    float cx = fminf(fmaxf(x, -15.f), 15.f);
    float e = __expf(2.f * cx);
    return __fdividef(e - 1.f, e + 1.f);
}

// ---------------- K1: hp = x @ Wlin^T ; row N1-1 = prior ----------------
__global__ __launch_bounds__(256) void k1_selflinear(const float* __restrict__ x,
                                                     const float* __restrict__ prior,
                                                     const float* __restrict__ Wlin) {
    __shared__ float xs[32][33];
    __shared__ float ws[128][33];
    const int b = blockIdx.y;
    const int nb = blockIdx.x * 32;
    const int t = threadIdx.x;
    const int tr = t >> 5;
    const int tc = t & 31;

    float acc[4][4];
#pragma unroll
    for (int a = 0; a < 4; ++a)
#pragma unroll
        for (int c = 0; c < 4; ++c) acc[a][c] = 0.f;

    for (int kb = 0; kb < Ii; kb += 32) {
        __syncthreads();
#pragma unroll
        for (int it = 0; it < 4; ++it) {
            int idx = t + 256 * it;
            int r = idx >> 5, k = idx & 31;
            int gn = nb + r;
            xs[r][k] = (gn < Nn) ? x[(b * Nn + gn) * Ii + kb + k] : 0.f;
        }
#pragma unroll
        for (int it = 0; it < 16; ++it) {
            int idx = t + 256 * it;
            int p = idx >> 5, k = idx & 31;
            ws[p][k] = Wlin[p * Ii + kb + k];
        }
        __syncthreads();
#pragma unroll
        for (int k = 0; k < 32; ++k) {
            float xv[4], wv[4];
#pragma unroll
            for (int a = 0; a < 4; ++a) xv[a] = xs[4 * tr + a][k];
#pragma unroll
            for (int c = 0; c < 4; ++c) wv[c] = ws[tc + 32 * c][k];
#pragma unroll
            for (int a = 0; a < 4; ++a)
#pragma unroll
                for (int c = 0; c < 4; ++c) acc[a][c] = fmaf(xv[a], wv[c], acc[a][c]);
        }
    }
#pragma unroll
    for (int a = 0; a < 4; ++a) {
        int gn = nb + 4 * tr + a;
#pragma unroll
        for (int c = 0; c < 4; ++c) {
            int col = tc + 32 * c;
            g_hp[(b * N1 + gn) * Oo + col] = (gn == Nn) ? prior[b * Oo + col] : acc[a][c];
        }
    }
}

// ---------------- K2: hph + fused tanh-dot scores ----------------
__global__ __launch_bounds__(256) void k2_headproj(const float* __restrict__ whead,
                                                   const float* __restrict__ asrc,
                                                   const float* __restrict__ adst) {
    __shared__ float as_[32][33];
    __shared__ float ws[32][128];
    const int nb = blockIdx.x * 32;
    const int h = blockIdx.y;
    const int b = blockIdx.z;
    const int t = threadIdx.x;
    const int tr = t >> 5;
    const int tc = t & 31;

    float acc[4][4];
#pragma unroll
    for (int a = 0; a < 4; ++a)
#pragma unroll
        for (int c = 0; c < 4; ++c) acc[a][c] = 0.f;

    for (int kb = 0; kb < Oo; kb += 32) {
        __syncthreads();
#pragma unroll
        for (int it = 0; it < 4; ++it) {
            int idx = t + 256 * it;
            int r = idx >> 5, k = idx & 31;
            as_[r][k] = g_hp[(b * N1 + nb + r) * Oo + kb + k];
        }
#pragma unroll
        for (int it = 0; it < 16; ++it) {
            int idx = t + 256 * it;
            int o = idx >> 7, p = idx & 127;
            ws[o][p] = whead[(h * Oo + kb + o) * Oo + p];
        }
        __syncthreads();
#pragma unroll
        for (int k = 0; k < 32; ++k) {
            float xv[4], wv[4];
#pragma unroll
            for (int a = 0; a < 4; ++a) xv[a] = as_[4 * tr + a][k];
#pragma unroll
            for (int c = 0; c < 4; ++c) wv[c] = ws[k][tc + 32 * c];
#pragma unroll
            for (int a = 0; a < 4; ++a)
#pragma unroll
                for (int c = 0; c < 4; ++c) acc[a][c] = fmaf(xv[a], wv[c], acc[a][c]);
        }
    }
    const int bh = b * Hh + h;
#pragma unroll
    for (int a = 0; a < 4; ++a) {
        int gn = nb + 4 * tr + a;
        float ps = 0.f, pd = 0.f;
#pragma unroll
        for (int c = 0; c < 4; ++c) {
            int col = tc + 32 * c;
            float v = acc[a][c];
            g_hph[(bh * N1 + gn) * Oo + col] = v;
            float tv = fast_tanh(v);
            ps = fmaf(tv, asrc[h * Oo + col], ps);
            pd = fmaf(tv, adst[h * Oo + col], pd);
        }
#pragma unroll
        for (int off = 16; off; off >>= 1) {
            ps += __shfl_xor_sync(0xffffffffu, ps, off);
            pd += __shfl_xor_sync(0xffffffffu, pd, off);
        }
        if (tc == 0) {
            int idx = bh * N1 + gn;
            g_ssrc[idx] = ps;
            g_sdst[idx] = pd;
        }
    }
}

// ---------------- K2b: mhp0[b,o] = mean over n of hp ----------------
__global__ __launch_bounds__(1024) void k2b_meanhp0() {
    __shared__ float red[1024];
    const int b = blockIdx.x;
    const int t = threadIdx.x;
    const int col = t & 127;
    const int seg = t >> 7;
    const float* p = g_hp + ((size_t)b * N1 + seg * 256) * Oo + col;
    float s = 0.f;
#pragma unroll 4
    for (int i = 0; i < 256; ++i) s += p[i * Oo];
    red[t] = s;
    __syncthreads();
    if (t < 128) {
        float tot = 0.f;
#pragma unroll
        for (int sgi = 0; sgi < 8; ++sgi) tot += red[col + 128 * sgi];
        g_mhp0[b * Oo + col] = tot * (1.f / (float)N1);
    }
}

// ---------------- K2c: meanhp[b,h] = mhp0[b] @ w_head[h] ----------------
__global__ __launch_bounds__(128) void k2c_meanhp(const float* __restrict__ whead) {
    __shared__ float m0[Oo];
    const int h = blockIdx.x;
    const int b = blockIdx.y;
    const int t = threadIdx.x;
    m0[t] = g_mhp0[b * Oo + t];
    __syncthreads();
    float s = 0.f;
#pragma unroll 8
    for (int o = 0; o < Oo; ++o) s = fmaf(m0[o], whead[(h * Oo + o) * Oo + t], s);
    g_meanhp[(b * Hh + h) * Oo + t] = s;
}

// ---------------- K3m: Mdst + all row/col factors ----------------
__global__ __launch_bounds__(256) void k3m_rowfac(const void* __restrict__ xmask) {
    __shared__ float red8[8];
    const int h = blockIdx.x;
    const int b = blockIdx.y;
    const int t = threadIdx.x;
    const int bh = b * Hh + h;

    float mx = -INFINITY;
    for (int n = t; n < N1; n += 256)
        if (!mask_at(xmask, b * N1 + n)) mx = fmaxf(mx, g_sdst[bh * N1 + n]);
#pragma unroll
    for (int off = 16; off; off >>= 1) mx = fmaxf(mx, __shfl_xor_sync(0xffffffffu, mx, off));
    if ((t & 31) == 0) red8[t >> 5] = mx;
    __syncthreads();
    if (t == 0) {
        float m = red8[0];
#pragma unroll
        for (int i = 1; i < 8; ++i) m = fmaxf(m, red8[i]);
        red8[0] = m;
    }
    __syncthreads();
    const float Mdst = red8[0];
    const bool nou = (Mdst == -INFINITY);

    for (int n = t; n < N1; n += 256) {
        int idx = bh * N1 + n;
        float sd = g_sdst[idx];
        float si = g_ssrc[idx];
        bool mj = mask_at(xmask, b * N1 + n);
        bool dead = mj || nou;
        // column factors (<=1 after Mdst subtraction)
        g_Ej[idx] = dead ? 0.f : expf(sd - Mdst);
        g_Fj[idx] = dead ? 0.f : expf(SLOPEF * (sd - Mdst));
        // row factors: p_E = Ei*Ej, p_F = Fi*Fj with m_i = lrelu(si + Mdst)
        float xm = si + Mdst;
        float m = (xm >= 0.f) ? xm : SLOPEF * xm;
        g_Ei[idx] = dead ? 0.f : expf(xm - m);
        g_Fi[idx] = dead ? 0.f : expf(SLOPEF * xm - m);
        g_runi[idx] = dead ? 1 : 0;
    }
}

// ---------------- KSort: per (b,h) bitonic sort of s_dst (+ gather wE/wF) ----------------
__global__ __launch_bounds__(1024) void ksort() {
    __shared__ float key[N1];
    __shared__ int idx[N1];
    const int bh = blockIdx.x;
    const int t = threadIdx.x;

    key[t] = g_sdst[bh * N1 + t];
    key[t + 1024] = g_sdst[bh * N1 + t + 1024];
    idx[t] = t;
    idx[t + 1024] = t + 1024;
    __syncthreads();

    for (int k = 2; k <= N1; k <<= 1) {
        for (int j = k >> 1; j > 0; j >>= 1) {
#pragma unroll 2
            for (int i = t; i < N1; i += 1024) {
                int ixj = i ^ j;
                if (ixj > i) {
                    bool up = ((i & k) == 0);
                    float ki = key[i], kj = key[ixj];
                    if (up ? (ki > kj) : (ki < kj)) {
                        key[i] = kj; key[ixj] = ki;
                        int tmp = idx[i]; idx[i] = idx[ixj]; idx[ixj] = tmp;
                    }
                }
            }
            __syncthreads();
        }
    }
    // write sorted keys + gathered weights
    for (int r = t; r < N1; r += 1024) {
        int j = idx[r];
        g_skey[bh * N1 + r] = key[r];
        g_sidx[bh * N1 + r] = j;
        g_wE[bh * N1 + r] = g_Ej[bh * N1 + j];
        g_wF[bh * N1 + r] = g_Fj[bh * N1 + j];
    }
}

// ---------------- KScan: segmented vector scans of wE*hph (suffix) & wF*hph (prefix) --------
__global__ __launch_bounds__(256) void kscan() {
    __shared__ float wE[SEGLEN], wF[SEGLEN];
    __shared__ int sidx[SEGLEN];
    const int s = blockIdx.x;    // segment
    const int bh = blockIdx.y;
    const int t = threadIdx.x;
    const int col = t & 127;
    const int job = t >> 7;      // 0 = F-prefix, 1 = E-suffix

    {
        int r = s * SEGLEN + t;
        if (t < SEGLEN) {
            wE[t] = g_wE[bh * N1 + r];
            wF[t] = g_wF[bh * N1 + r];
            sidx[t] = g_sidx[bh * N1 + r];
        }
    }
    __syncthreads();

    const float* hph = g_hph + (size_t)bh * N1 * Oo;
    const size_t outbase = ((size_t)bh * NP1 + s * SEGLEN) * Oo;

    if (job == 0) {
        // prefix of wF*hph: write PF[segstart + r + 1] = sum_{r' <= r, local}
        float acc = 0.f, sacc = 0.f;
#pragma unroll 4
        for (int r = 0; r < SEGLEN; ++r) {
            float v = hph[(size_t)sidx[r] * Oo + col];
            acc = fmaf(wF[r], v, acc);
            g_PF[outbase + (size_t)(r + 1) * Oo + col] = acc;
            if (col == 0) {
                sacc += wF[r];
                g_sPF[bh * NP1 + s * SEGLEN + r + 1] = sacc;
            }
        }
    } else {
        // suffix of wE*hph: write SE[segstart + r] = sum_{r' >= r, local}
        float acc = 0.f, sacc = 0.f;
#pragma unroll 4
        for (int r = SEGLEN - 1; r >= 0; --r) {
            float v = hph[(size_t)sidx[r] * Oo + col];
            acc = fmaf(wE[r], v, acc);
            g_SE[outbase + (size_t)r * Oo + col] = acc;
            if (col == 0) {
                sacc += wE[r];
                g_sSE[bh * NP1 + s * SEGLEN + r] = sacc;
            }
        }
    }
}

// ---------------- KOff: per-segment offset vectors ----------------
__global__ __launch_bounds__(128) void koff() {
    const int bh = blockIdx.x;
    const int col = threadIdx.x;
    float acc = 0.f;
    for (int s = SEGS - 1; s >= 0; --s) {
        g_offE[(bh * SEGS + s) * Oo + col] = acc;
        acc += g_SE[((size_t)bh * NP1 + s * SEGLEN) * Oo + col];
    }
    float accF = 0.f;
    for (int s = 0; s < SEGS; ++s) {
        g_offF[(bh * SEGS + s) * Oo + col] = accF;
        accF += g_PF[((size_t)bh * NP1 + s * SEGLEN + SEGLEN) * Oo + col];
    }
    if (col == 0) {
        float a = 0.f;
        for (int s = SEGS - 1; s >= 0; --s) {
            g_soffE[bh * SEGS + s] = a;
            a += g_sSE[bh * NP1 + s * SEGLEN];
        }
        float aF = 0.f;
        for (int s = 0; s < SEGS; ++s) {
            g_soffF[bh * SEGS + s] = aF;
            aF += g_sPF[bh * NP1 + s * SEGLEN + SEGLEN];
        }
    }
}

// ---------------- KOut: threshold lookup + combine + head-mean + bias ----------------
__global__ __launch_bounds__(256) void kout(const float* __restrict__ bias,
                                            float* __restrict__ out) {
    __shared__ float keys[N1];     // 8 KB sorted keys
    __shared__ float mhs[Oo];
    __shared__ int tis[32];
    __shared__ float Eis[32], Fis[32], invl[32];
    __shared__ unsigned char runi[32];

    const int ib = blockIdx.x;
    const int b = blockIdx.y;
    const int t = threadIdx.x;
    const int col = t & 127;
    const int rh = t >> 7;         // 0/1; thread handles rows rh + 2*rr

    float sum[16];
#pragma unroll
    for (int rr = 0; rr < 16; ++rr) sum[rr] = 0.f;

    for (int h = 0; h < Hh; ++h) {
        const int bh = b * Hh + h;
        __syncthreads();
        for (int i = t; i < N1; i += 256) keys[i] = g_skey[bh * N1 + i];
        if (t < Oo) mhs[t] = g_meanhp[bh * Oo + t];
        __syncthreads();

        if (t < 32) {
            int gi = ib * 32 + t;
            int idx = bh * N1 + gi;
            float si = g_ssrc[idx];
            float target = -si;
            int lo = 0, hi = N1;
            while (lo < hi) {
                int mid = (lo + hi) >> 1;
                if (keys[mid] >= target) hi = mid; else lo = mid + 1;
            }
            int ti = lo;
            float Ei = g_Ei[idx], Fi = g_Fi[idx];
            float sse = (ti == N1) ? 0.f : g_sSE[bh * NP1 + ti] + g_soffE[bh * SEGS + (ti >> 8)];
            float spf = (ti == 0) ? 0.f : g_sPF[bh * NP1 + ti] + g_soffF[bh * SEGS + ((ti - 1) >> 8)];
            float li = Ei * sse + Fi * spf;
            tis[t] = ti;
            Eis[t] = Ei;
            Fis[t] = Fi;
            invl[t] = 1.f / li;
            runi[t] = g_runi[idx];
        }
        __syncthreads();

#pragma unroll 4
        for (int rr = 0; rr < 16; ++rr) {
            int r = rh + 2 * rr;
            if (runi[r]) { sum[rr] += mhs[col]; continue; }
            int ti = tis[r];
            float se = (ti == N1) ? 0.f
                : g_SE[((size_t)bh * NP1 + ti) * Oo + col] + g_offE[(bh * SEGS + (ti >> 8)) * Oo + col];
            float pf = (ti == 0) ? 0.f
                : g_PF[((size_t)bh * NP1 + ti) * Oo + col] + g_offF[(bh * SEGS + ((ti - 1) >> 8)) * Oo + col];
            sum[rr] += (Eis[r] * se + Fis[r] * pf) * invl[r];
        }
    }

    float* outp = out + ((size_t)b * N1 + ib * 32) * Oo;
#pragma unroll
    for (int rr = 0; rr < 16; ++rr) {
        int r = rh + 2 * rr;
        outp[r * Oo + col] = 0.25f * sum[rr] + bias[col];
    }
}

// ---------------- launch ----------------
extern "C" void kernel_launch(void* const* d_in, const int* in_sizes, int n_in,
                              void* d_out, int out_size) {
    const float* x = (const float*)d_in[0];
    const float* prior = (const float*)d_in[1];
    const void* xmask = d_in[2];
    const float* Wlin = (const float*)d_in[3];
    const float* whead = (const float*)d_in[4];
    const float* asrc = (const float*)d_in[5];
    const float* adst = (const float*)d_in[6];
    const float* bias = (const float*)d_in[7];
    float* out = (float*)d_out;

    kinit_maskflag<<<1, 1>>>();
    kdetect_mask<<<8, 256>>>((const unsigned*)xmask);
    k1_selflinear<<<dim3(64, Bb), 256>>>(x, prior, Wlin);
    k2_headproj<<<dim3(64, Hh, Bb), 256>>>(whead, asrc, adst);
    k2b_meanhp0<<<Bb, 1024>>>();
    k2c_meanhp<<<dim3(Hh, Bb), 128>>>(whead);
    k3m_rowfac<<<dim3(Hh, Bb), 256>>>(xmask);
    ksort<<<NBH, 1024>>>();
    kscan<<<dim3(SEGS, NBH), 256>>>();
    koff<<<NBH, 128>>>();
    kout<<<dim3(64, Bb), 256>>>(bias, out);
}

// round 5
// speedup vs baseline: 3.7572x; 1.3236x over previous
#include <cuda_runtime.h>
#include <math.h>

#define Bb 4
#define Nn 2047
#define N1 2048
#define Ii 256
#define Oo 128
#define Hh 4
#define SLOPEF 0.2f
#define NBH (Bb * Hh)
#define SEGS 8
#define SEGLEN 256
#define NP1 2049

typedef unsigned long long ull;

// ---------------- scratch (device globals) ----------------
__device__ float g_hp[Bb * N1 * Oo];            // 4 MB (for meanhp path)
__device__ float g_hph[Bb * Hh * N1 * Oo];      // 16 MB
__device__ float g_ssrc[NBH * N1];
__device__ float g_sdst[NBH * N1];
__device__ float g_Ei[NBH * N1], g_Fi[NBH * N1];
__device__ unsigned char g_runi[NBH * N1];
__device__ float g_mhp0[Bb * Oo];
__device__ float g_meanhp[NBH * Oo];
__device__ float g_skey[NBH * N1];
__device__ int   g_sidx[NBH * N1];
__device__ float g_wE[NBH * N1], g_wF[NBH * N1];
__device__ float g_SE[(size_t)NBH * NP1 * Oo];
__device__ float g_PF[(size_t)NBH * NP1 * Oo];
__device__ float g_sSE[NBH * NP1], g_sPF[NBH * NP1];
__device__ float g_offE[NBH * SEGS * Oo], g_offF[NBH * SEGS * Oo];
__device__ float g_soffE[NBH * SEGS], g_soffF[NBH * SEGS];
__device__ int g_mask_is_int;

// ---------------- mask dtype detection ----------------
__global__ void kinit_maskflag() { g_mask_is_int = 1; }
__global__ void kdetect_mask(const unsigned* __restrict__ m) {
    int idx = blockIdx.x * 256 + threadIdx.x;   // 2048 words = 8192 bytes, safe either way
    if (m[idx] > 1u) g_mask_is_int = 0;
}
__device__ __forceinline__ bool mask_at(const void* m, int idx) {
    if (g_mask_is_int) return ((const int*)m)[idx] != 0;
    return ((const unsigned char*)m)[idx] != 0;
}

__device__ __forceinline__ float fast_tanh(float x) {
    float cx = fminf(fmaxf(x, -15.f), 15.f);
    float e = __expf(2.f * cx);
    return __fdividef(e - 1.f, e + 1.f);
}

__device__ __forceinline__ ull packf2(float v) {
    ull r;
    asm("mov.b64 %0, {%1, %1};" : "=l"(r) : "f"(v));
    return r;
}
__device__ __forceinline__ void fma2(ull& d, ull a, ull b) {
    asm("fma.rn.f32x2 %0, %1, %2, %0;" : "+l"(d) : "l"(a), "l"(b));
}
__device__ __forceinline__ void unpackf2(ull v, float& lo, float& hi) {
    asm("mov.b64 {%0, %1}, %2;" : "=f"(lo), "=f"(hi) : "l"(v));
}

// ---------------- K12: fused self_linear + head projection + scores ----------------
// Block: 256 threads, 32-row tile. Phase A: hp tile (K=256). Phase B: 4 heads (K=128).
// Thread map: tr = t>>4 -> rows {tr, tr+16}; tc = t&15 -> col pairs {2tc+32c}, c<4.
__global__ __launch_bounds__(256) void k12_fused(const float* __restrict__ x,
                                                 const float* __restrict__ prior,
                                                 const float* __restrict__ Wlin,
                                                 const float* __restrict__ whead,
                                                 const float* __restrict__ asrc,
                                                 const float* __restrict__ adst) {
    __shared__ float xs[32][33];
    __shared__ float ws2[32][130];   // phase A: W^T chunk [k][p]; phase B: w_head chunk [o][p]
    __shared__ float hpt[32][130];   // hp tile (rows x 128 cols, pad 2)

    const int ib = blockIdx.x;
    const int nb = ib * 32;
    const int b = blockIdx.y;
    const int t = threadIdx.x;
    const int tr = t >> 4;
    const int tc = t & 15;

    // ---- Phase A: hp tile ----
    ull acc[2][4];
#pragma unroll
    for (int ar = 0; ar < 2; ++ar)
#pragma unroll
        for (int c = 0; c < 4; ++c) acc[ar][c] = 0ull;

    for (int kb = 0; kb < Ii; kb += 32) {
        __syncthreads();
#pragma unroll
        for (int it = 0; it < 4; ++it) {
            int idx = t + 256 * it;
            int r = idx >> 5, k = idx & 31;
            int gn = nb + r;
            xs[r][k] = (gn < Nn) ? x[(b * Nn + gn) * Ii + kb + k] : 0.f;
        }
#pragma unroll
        for (int it = 0; it < 16; ++it) {
            int idx = t + 256 * it;
            int p = idx >> 5, k = idx & 31;
            ws2[k][p] = Wlin[p * Ii + kb + k];   // transposed store
        }
        __syncthreads();
#pragma unroll
        for (int k = 0; k < 32; ++k) {
            ull pp0 = packf2(xs[tr][k]);
            ull pp1 = packf2(xs[tr + 16][k]);
#pragma unroll
            for (int c = 0; c < 4; ++c) {
                ull wv = *(const ull*)&ws2[k][2 * tc + 32 * c];
                fma2(acc[0][c], pp0, wv);
                fma2(acc[1][c], pp1, wv);
            }
        }
    }
    // epilogue A: prior row substitution, store to smem + g_hp
#pragma unroll
    for (int ar = 0; ar < 2; ++ar) {
        int r = tr + 16 * ar;
        int gn = nb + r;
        bool isprior = (gn == Nn);
#pragma unroll
        for (int c = 0; c < 4; ++c) {
            int col = 2 * tc + 32 * c;
            float lo, hi;
            unpackf2(acc[ar][c], lo, hi);
            if (isprior) { lo = prior[b * Oo + col]; hi = prior[b * Oo + col + 1]; }
            hpt[r][col] = lo;
            hpt[r][col + 1] = hi;
            *(float2*)&g_hp[(size_t)(b * N1 + gn) * Oo + col] = make_float2(lo, hi);
        }
    }

    // ---- Phase B: per-head projection + scores ----
    for (int h = 0; h < Hh; ++h) {
        ull a2[2][4];
#pragma unroll
        for (int ar = 0; ar < 2; ++ar)
#pragma unroll
            for (int c = 0; c < 4; ++c) a2[ar][c] = 0ull;

        for (int kb = 0; kb < Oo; kb += 32) {
            __syncthreads();
#pragma unroll
            for (int it = 0; it < 16; ++it) {
                int idx = t + 256 * it;
                int o = idx >> 7, p = idx & 127;
                ws2[o][p] = whead[(size_t)(h * Oo + kb + o) * Oo + p];
            }
            __syncthreads();
#pragma unroll
            for (int k = 0; k < 32; ++k) {
                ull pp0 = packf2(hpt[tr][kb + k]);
                ull pp1 = packf2(hpt[tr + 16][kb + k]);
#pragma unroll
                for (int c = 0; c < 4; ++c) {
                    ull wv = *(const ull*)&ws2[k][2 * tc + 32 * c];
                    fma2(a2[0][c], pp0, wv);
                    fma2(a2[1][c], pp1, wv);
                }
            }
        }
        // epilogue B: write hph, fused tanh-dot scores
        const int bh = b * Hh + h;
#pragma unroll
        for (int ar = 0; ar < 2; ++ar) {
            int r = tr + 16 * ar;
            int gn = nb + r;
            float ps = 0.f, pd = 0.f;
#pragma unroll
            for (int c = 0; c < 4; ++c) {
                int col = 2 * tc + 32 * c;
                float lo, hi;
                unpackf2(a2[ar][c], lo, hi);
                *(float2*)&g_hph[((size_t)bh * N1 + gn) * Oo + col] = make_float2(lo, hi);
                float t0 = fast_tanh(lo);
                float t1 = fast_tanh(hi);
                ps = fmaf(t0, asrc[h * Oo + col], fmaf(t1, asrc[h * Oo + col + 1], ps));
                pd = fmaf(t0, adst[h * Oo + col], fmaf(t1, adst[h * Oo + col + 1], pd));
            }
#pragma unroll
            for (int off = 8; off; off >>= 1) {
                ps += __shfl_xor_sync(0xffffffffu, ps, off);
                pd += __shfl_xor_sync(0xffffffffu, pd, off);
            }
            if (tc == 0) {
                g_ssrc[bh * N1 + gn] = ps;
                g_sdst[bh * N1 + gn] = pd;
            }
        }
    }
}

// ---------------- K2b: mhp0[b,o] = mean over n of hp ----------------
__global__ __launch_bounds__(1024) void k2b_meanhp0() {
    __shared__ float red[1024];
    const int b = blockIdx.x;
    const int t = threadIdx.x;
    const int col = t & 127;
    const int seg = t >> 7;
    const float* p = g_hp + ((size_t)b * N1 + seg * 256) * Oo + col;
    float s = 0.f;
#pragma unroll 4
    for (int i = 0; i < 256; ++i) s += p[i * Oo];
    red[t] = s;
    __syncthreads();
    if (t < 128) {
        float tot = 0.f;
#pragma unroll
        for (int sgi = 0; sgi < 8; ++sgi) tot += red[col + 128 * sgi];
        g_mhp0[b * Oo + col] = tot * (1.f / (float)N1);
    }
}

// ---------------- K2c: meanhp[b,h] = mhp0[b] @ w_head[h] ----------------
__global__ __launch_bounds__(128) void k2c_meanhp(const float* __restrict__ whead) {
    __shared__ float m0[Oo];
    const int h = blockIdx.x;
    const int b = blockIdx.y;
    const int t = threadIdx.x;
    m0[t] = g_mhp0[b * Oo + t];
    __syncthreads();
    float s = 0.f;
#pragma unroll 8
    for (int o = 0; o < Oo; ++o) s = fmaf(m0[o], whead[(h * Oo + o) * Oo + t], s);
    g_meanhp[(b * Hh + h) * Oo + t] = s;
}

// ---------------- KSortM: fused factors (Mdst, Ei/Fi/Ej/Fj/runi) + bitonic sort ------------
__global__ __launch_bounds__(1024) void ksortm(const void* __restrict__ xmask) {
    __shared__ float key[N1];
    __shared__ int idx[N1];
    __shared__ float Ejs[N1], Fjs[N1];
    __shared__ float red32[32];
    const int bh = blockIdx.x;
    const int b = bh / Hh;
    const int t = threadIdx.x;

    // Mdst = max over unmasked j of s_dst
    float mx = -INFINITY;
#pragma unroll
    for (int n = t; n < N1; n += 1024)
        if (!mask_at(xmask, b * N1 + n)) mx = fmaxf(mx, g_sdst[bh * N1 + n]);
#pragma unroll
    for (int off = 16; off; off >>= 1) mx = fmaxf(mx, __shfl_xor_sync(0xffffffffu, mx, off));
    if ((t & 31) == 0) red32[t >> 5] = mx;
    __syncthreads();
    if (t == 0) {
        float m = red32[0];
#pragma unroll
        for (int i = 1; i < 32; ++i) m = fmaxf(m, red32[i]);
        red32[0] = m;
    }
    __syncthreads();
    const float Mdst = red32[0];
    const bool nou = (Mdst == -INFINITY);

    // factors
#pragma unroll
    for (int n = t; n < N1; n += 1024) {
        int gidx = bh * N1 + n;
        float sd = g_sdst[gidx];
        float si = g_ssrc[gidx];
        bool dead = nou || mask_at(xmask, b * N1 + n);
        Ejs[n] = dead ? 0.f : expf(sd - Mdst);
        Fjs[n] = dead ? 0.f : expf(SLOPEF * (sd - Mdst));
        float xm = si + Mdst;
        float m = (xm >= 0.f) ? xm : SLOPEF * xm;
        g_Ei[gidx] = dead ? 0.f : expf(xm - m);
        g_Fi[gidx] = dead ? 0.f : expf(SLOPEF * xm - m);
        g_runi[gidx] = dead ? 1 : 0;
        key[n] = sd;
        idx[n] = n;
    }
    __syncthreads();

    // bitonic sort ascending by key
    for (int k = 2; k <= N1; k <<= 1) {
        for (int j = k >> 1; j > 0; j >>= 1) {
#pragma unroll 2
            for (int i = t; i < N1; i += 1024) {
                int ixj = i ^ j;
                if (ixj > i) {
                    bool up = ((i & k) == 0);
                    float ki = key[i], kj = key[ixj];
                    if (up ? (ki > kj) : (ki < kj)) {
                        key[i] = kj; key[ixj] = ki;
                        int tmp = idx[i]; idx[i] = idx[ixj]; idx[ixj] = tmp;
                    }
                }
            }
            __syncthreads();
        }
    }
#pragma unroll
    for (int r = t; r < N1; r += 1024) {
        int j = idx[r];
        g_skey[bh * N1 + r] = key[r];
        g_sidx[bh * N1 + r] = j;
        g_wE[bh * N1 + r] = Ejs[j];
        g_wF[bh * N1 + r] = Fjs[j];
    }
}

// ---------------- KScan: segmented scans of wE*hph (suffix) & wF*hph (prefix) ----------------
__global__ __launch_bounds__(256) void kscan() {
    __shared__ float wE[SEGLEN], wF[SEGLEN];
    __shared__ int sidx[SEGLEN];
    const int s = blockIdx.x;
    const int bh = blockIdx.y;
    const int t = threadIdx.x;
    const int col = t & 127;
    const int job = t >> 7;

    {
        int r = s * SEGLEN + t;
        if (t < SEGLEN) {
            wE[t] = g_wE[bh * N1 + r];
            wF[t] = g_wF[bh * N1 + r];
            sidx[t] = g_sidx[bh * N1 + r];
        }
    }
    __syncthreads();

    const float* hph = g_hph + (size_t)bh * N1 * Oo;
    const size_t outbase = ((size_t)bh * NP1 + s * SEGLEN) * Oo;

    if (job == 0) {
        float acc = 0.f, sacc = 0.f;
#pragma unroll 4
        for (int r = 0; r < SEGLEN; ++r) {
            float v = hph[(size_t)sidx[r] * Oo + col];
            acc = fmaf(wF[r], v, acc);
            g_PF[outbase + (size_t)(r + 1) * Oo + col] = acc;
            if (col == 0) {
                sacc += wF[r];
                g_sPF[bh * NP1 + s * SEGLEN + r + 1] = sacc;
            }
        }
    } else {
        float acc = 0.f, sacc = 0.f;
#pragma unroll 4
        for (int r = SEGLEN - 1; r >= 0; --r) {
            float v = hph[(size_t)sidx[r] * Oo + col];
            acc = fmaf(wE[r], v, acc);
            g_SE[outbase + (size_t)r * Oo + col] = acc;
            if (col == 0) {
                sacc += wE[r];
                g_sSE[bh * NP1 + s * SEGLEN + r] = sacc;
            }
        }
    }
}

// ---------------- KOff: per-segment offsets ----------------
__global__ __launch_bounds__(128) void koff() {
    const int bh = blockIdx.x;
    const int col = threadIdx.x;
    float acc = 0.f;
    for (int s = SEGS - 1; s >= 0; --s) {
        g_offE[(bh * SEGS + s) * Oo + col] = acc;
        acc += g_SE[((size_t)bh * NP1 + s * SEGLEN) * Oo + col];
    }
    float accF = 0.f;
    for (int s = 0; s < SEGS; ++s) {
        g_offF[(bh * SEGS + s) * Oo + col] = accF;
        accF += g_PF[((size_t)bh * NP1 + s * SEGLEN + SEGLEN) * Oo + col];
    }
    if (col == 0) {
        float a = 0.f;
        for (int s = SEGS - 1; s >= 0; --s) {
            g_soffE[bh * SEGS + s] = a;
            a += g_sSE[bh * NP1 + s * SEGLEN];
        }
        float aF = 0.f;
        for (int s = 0; s < SEGS; ++s) {
            g_soffF[bh * SEGS + s] = aF;
            aF += g_sPF[bh * NP1 + s * SEGLEN + SEGLEN];
        }
    }
}

// ---------------- KOut: threshold lookup + combine + head-mean + bias ----------------
__global__ __launch_bounds__(256) void kout(const float* __restrict__ bias,
                                            float* __restrict__ out) {
    __shared__ float keys[N1];
    __shared__ float mhs[Oo];
    __shared__ int tis[32];
    __shared__ float Eis[32], Fis[32], invl[32];
    __shared__ unsigned char runi[32];

    const int ib = blockIdx.x;
    const int b = blockIdx.y;
    const int t = threadIdx.x;
    const int col = t & 127;
    const int rh = t >> 7;

    float sum[16];
#pragma unroll
    for (int rr = 0; rr < 16; ++rr) sum[rr] = 0.f;

    for (int h = 0; h < Hh; ++h) {
        const int bh = b * Hh + h;
        __syncthreads();
        for (int i = t; i < N1; i += 256) keys[i] = g_skey[bh * N1 + i];
        if (t < Oo) mhs[t] = g_meanhp[bh * Oo + t];
        __syncthreads();

        if (t < 32) {
            int gi = ib * 32 + t;
            int idx = bh * N1 + gi;
            float si = g_ssrc[idx];
            float target = -si;
            int lo = 0, hi = N1;
            while (lo < hi) {
                int mid = (lo + hi) >> 1;
                if (keys[mid] >= target) hi = mid; else lo = mid + 1;
            }
            int ti = lo;
            float Ei = g_Ei[idx], Fi = g_Fi[idx];
            float sse = (ti == N1) ? 0.f : g_sSE[bh * NP1 + ti] + g_soffE[bh * SEGS + (ti >> 8)];
            float spf = (ti == 0) ? 0.f : g_sPF[bh * NP1 + ti] + g_soffF[bh * SEGS + ((ti - 1) >> 8)];
            float li = Ei * sse + Fi * spf;
            tis[t] = ti;
            Eis[t] = Ei;
            Fis[t] = Fi;
            invl[t] = 1.f / li;
            runi[t] = g_runi[idx];
        }
        __syncthreads();

#pragma unroll 4
        for (int rr = 0; rr < 16; ++rr) {
            int r = rh + 2 * rr;
            if (runi[r]) { sum[rr] += mhs[col]; continue; }
            int ti = tis[r];
            float se = (ti == N1) ? 0.f
                : g_SE[((size_t)bh * NP1 + ti) * Oo + col] + g_offE[(bh * SEGS + (ti >> 8)) * Oo + col];
            float pf = (ti == 0) ? 0.f
                : g_PF[((size_t)bh * NP1 + ti) * Oo + col] + g_offF[(bh * SEGS + ((ti - 1) >> 8)) * Oo + col];
            sum[rr] += (Eis[r] * se + Fis[r] * pf) * invl[r];
        }
    }

    float* outp = out + ((size_t)b * N1 + ib * 32) * Oo;
#pragma unroll
    for (int rr = 0; rr < 16; ++rr) {
        int r = rh + 2 * rr;
        outp[r * Oo + col] = 0.25f * sum[rr] + bias[col];
    }
}

// ---------------- launch ----------------
extern "C" void kernel_launch(void* const* d_in, const int* in_sizes, int n_in,
                              void* d_out, int out_size) {
    const float* x = (const float*)d_in[0];
    const float* prior = (const float*)d_in[1];
    const void* xmask = d_in[2];
    const float* Wlin = (const float*)d_in[3];
    const float* whead = (const float*)d_in[4];
    const float* asrc = (const float*)d_in[5];
    const float* adst = (const float*)d_in[6];
    const float* bias = (const float*)d_in[7];
    float* out = (float*)d_out;

    kinit_maskflag<<<1, 1>>>();
    kdetect_mask<<<8, 256>>>((const unsigned*)xmask);
    k12_fused<<<dim3(64, Bb), 256>>>(x, prior, Wlin, whead, asrc, adst);
    k2b_meanhp0<<<Bb, 1024>>>();
    k2c_meanhp<<<dim3(Hh, Bb), 128>>>(whead);
    ksortm<<<NBH, 1024>>>(xmask);
    kscan<<<dim3(SEGS, NBH), 256>>>();
    koff<<<NBH, 128>>>();
    kout<<<dim3(64, Bb), 256>>>(bias, out);
}